// round 17
// baseline (speedup 1.0000x reference)
#include <cuda_runtime.h>
#include <cuda_fp16.h>
#include <cstdint>
#include <math.h>

// JAX PRNG scheme: jax_threefry_partitionable=True (verified R2-R15)
#define NPIX   50176            // 224*224
#define IMG    150528           // 3*NPIX
#define BATCH  64
#define NUM_IT 64
#define TOTAL  (BATCH * IMG)
#define NPAIRS 25088            // NPIX/2
#define SIGMA_F 0.05f
#define NSEG   7                 // tile split: 7 segments
#define SEG_PAIRS 3584           // 25088 / 7 = 3584 = 14 * 256 exactly

struct Keys { unsigned int k[2 * NUM_IT]; };

// Scratch (__device__ globals — sanctioned no-allocation path)
__device__ float g_logits_part[NSEG][(NUM_IT + 1) * BATCH];
__device__ float g_d[NUM_IT * BATCH];
__device__ float g_coef[BATCH];
// Merged per-pair operand record, 3 x float4 = 48 B:
//   [0] = {b0x,b0y,b1x,b1y}  [1] = {b2x,b2y,w0x,w0y}  [2] = {w1x,w1y,w2x,w2y}
__device__ float4 g_bw[(size_t)BATCH * NPAIRS * 3];   // 77 MB
// Normalized noise as half2(ch0, ch1) per pixel; ch2 = -(ch0+ch1). 822 MB.
__device__ unsigned int g_tn_h[(size_t)NUM_IT * BATCH * NPIX];

typedef unsigned long long u64;

// ---------------------------------------------------------------------------
// f32x2 packed helpers (sm_10x)
// ---------------------------------------------------------------------------
__device__ __forceinline__ u64 pk2(float a, float b) {
    u64 r; asm("mov.b64 %0,{%1,%2};" : "=l"(r) : "f"(a), "f"(b)); return r;
}
__device__ __forceinline__ void upk2(u64 v, float &a, float &b) {
    asm("mov.b64 {%0,%1},%2;" : "=f"(a), "=f"(b) : "l"(v));
}
__device__ __forceinline__ u64 fma2(u64 a, u64 b, u64 c) {
    u64 r; asm("fma.rn.f32x2 %0,%1,%2,%3;" : "=l"(r) : "l"(a), "l"(b), "l"(c)); return r;
}
__device__ __forceinline__ u64 add2(u64 a, u64 b) {
    u64 r; asm("add.rn.f32x2 %0,%1,%2;" : "=l"(r) : "l"(a), "l"(b)); return r;
}
__device__ __forceinline__ u64 mul2(u64 a, u64 b) {
    u64 r; asm("mul.rn.f32x2 %0,%1,%2;" : "=l"(r) : "l"(a), "l"(b)); return r;
}
__device__ __forceinline__ u64 sp2(float a) { return pk2(a, a); }

// scalar add with saturation to [0,1] in ONE FADD (fma pipe)
__device__ __forceinline__ float addsat(float a, float b) {
    float r; asm("add.rn.sat.f32 %0,%1,%2;" : "=f"(r) : "f"(a), "f"(b)); return r;
}
__device__ __forceinline__ float sat(float a) {
    float r; asm("add.rn.sat.f32 %0,%1,0f00000000;" : "=f"(r) : "f"(a)); return r;
}

// ---------------------------------------------------------------------------
// Host-side Threefry-2x32 (key derivation only)
// ---------------------------------------------------------------------------
static void tf2x32_host(unsigned int k0, unsigned int k1,
                        unsigned int x0, unsigned int x1,
                        unsigned int &o0, unsigned int &o1)
{
    unsigned int k2 = k0 ^ k1 ^ 0x1BD11BDAu;
    x0 += k0; x1 += k1;
#define TF_R(r) { x0 += x1; x1 = (x1 << (r)) | (x1 >> (32 - (r))); x1 ^= x0; }
    TF_R(13) TF_R(15) TF_R(26) TF_R(6)
    x0 += k1; x1 += k2 + 1u;
    TF_R(17) TF_R(29) TF_R(16) TF_R(24)
    x0 += k2; x1 += k0 + 2u;
    TF_R(13) TF_R(15) TF_R(26) TF_R(6)
    x0 += k0; x1 += k1 + 3u;
    TF_R(17) TF_R(29) TF_R(16) TF_R(24)
    x0 += k1; x1 += k2 + 4u;
    TF_R(13) TF_R(15) TF_R(26) TF_R(6)
    x0 += k2; x1 += k0 + 5u;
#undef TF_R
    o0 = x0; o1 = x1;
}

// ---------------------------------------------------------------------------
// Integer ops pinned to the fma pipe (IMAD/IMAD.HI) via opaque `one`
// ---------------------------------------------------------------------------
__device__ __forceinline__ unsigned int madd(unsigned int a, unsigned int one,
                                             unsigned int b)
{
    unsigned int r;
    asm("mad.lo.u32 %0, %1, %2, %3;" : "=r"(r) : "r"(a), "r"(one), "r"(b));
    return r;
}
__device__ __forceinline__ unsigned int madhi(unsigned int a, unsigned int b,
                                              unsigned int c)
{
    unsigned int r;
    asm("mad.hi.u32 %0, %1, %2, %3;" : "=r"(r) : "r"(a), "r"(b), "r"(c));
    return r;
}

// Threefry-2x32, counter (0, j), partitionable output x0^x1.  (R10 exact.)
__device__ __forceinline__ unsigned int rbits_m(
    unsigned int k0, unsigned int k1, unsigned int k2,
    unsigned int j, unsigned int one)
{
    unsigned int x0 = k0;                    // counter hi = 0
    unsigned int x1 = madd(j, one, k1);      // counter lo = j
#define TF_RM(r) { x0 = madd(x1, one, x0); \
                   x1 = (x1 << (r)) | (x1 >> (32 - (r))); x1 ^= x0; }
    TF_RM(13) TF_RM(15) TF_RM(26) TF_RM(6)
    x0 = madd(x0, one, k1); x1 = madd(x1, one, k2 + 1u);
    TF_RM(17) TF_RM(29) TF_RM(16) TF_RM(24)
    x0 = madd(x0, one, k2); x1 = madd(x1, one, k0 + 2u);
    TF_RM(13) TF_RM(15) TF_RM(26) TF_RM(6)
    x0 = madd(x0, one, k0); x1 = madd(x1, one, k1 + 3u);
    TF_RM(17) TF_RM(29) TF_RM(16) TF_RM(24)
    x0 = madd(x0, one, k1); x1 = madd(x1, one, k2 + 4u);
    TF_RM(13) TF_RM(15) TF_RM(26) TF_RM(6)
    x0 = madd(x0, one, k2); x1 = madd(x1, one, k0 + 5u);
#undef TF_RM
    return x0 ^ x1;
}

// Tail fixup (w >= 5): XLA's Giles tail polynomial, scalar, inline, rare.
__device__ __forceinline__ float tail_fix(float w, float x)
{
    float s = sqrtf(w) - 3.0f;
    float p =          -0.000200214257f;
    p = fmaf(p, s, 0.000100950558f);
    p = fmaf(p, s, 0.00134934322f);
    p = fmaf(p, s, -0.00367342844f);
    p = fmaf(p, s, 0.00573950773f);
    p = fmaf(p, s, -0.0076224613f);
    p = fmaf(p, s, 0.00943887047f);
    p = fmaf(p, s, 1.00167406f);
    p = fmaf(p, s, 2.83297682f);
    return p * x;
}

// Packed normals (erfinv/sqrt2-scaled); ln2 scale and -2.5 shift folded into
// transformed Giles coefficients, Horner variable zz = log2(1-u^2) + 2.5/ln2.
__device__ __forceinline__ u64 normal2(unsigned int ba, unsigned int bb)
{
    // (bits>>9)|0x3f800000 == mad.hi(bits, 1<<23, 0x3f800000)  (fma pipe)
    unsigned int ia = madhi(ba, 0x00800000u, 0x3f800000u);
    unsigned int ib = madhi(bb, 0x00800000u, 0x3f800000u);
    u64 v = pk2(__uint_as_float(ia), __uint_as_float(ib));
    u64 f = add2(v, sp2(-1.0f));                       // exact (Sterbenz)
    u64 u = fma2(f, sp2(2.0f), sp2(-0.99999994f));     // uniform in [lo,1)
    u64 s = fma2(u, u, sp2(-1.0f));                    // u^2-1 = -(1-u^2)
    float sa_, sb_; upk2(s, sa_, sb_);
    float za = __log2f(-sa_);                          // log2(1-u^2) <= 0
    float zb = __log2f(-sb_);
    u64 zz = add2(pk2(za, zb), sp2(3.6067376f));       // + 2.5/ln2

    u64 p = sp2(1.49742e-9f);                          // e8
    p = fma2(p, zz, sp2(-2.63893e-8f));                // e7
    p = fma2(p, zz, sp2(-3.90762e-7f));                // e6
    p = fma2(p, zz, sp2(7.02653e-7f));                 // e5
    p = fma2(p, zz, sp2(5.045614e-5f));                // e4
    p = fma2(p, zz, sp2(4.1752126e-4f));               // e3
    p = fma2(p, zz, sp2(-2.00718e-3f));                // e2
    p = fma2(p, zz, sp2(-0.17095832f));                // e1
    p = fma2(p, zz, sp2(1.50140941f));                 // e0
    u64 r = mul2(p, u);

    float zza, zzb; upk2(zz, zza, zzb);
    if (zza <= -3.6067376f || zzb <= -3.6067376f) {    // ~20% warp trigger
        float ra, rb, ua_, ub_;
        upk2(r, ra, rb); upk2(u, ua_, ub_);
        if (zza <= -3.6067376f)
            ra = tail_fix(fmaf(-0.6931472f, zza, 2.5f), ua_);
        if (zzb <= -3.6067376f)
            rb = tail_fix(fmaf(-0.6931472f, zzb, 2.5f), ub_);
        r = pk2(ra, rb);
    }
    return r;
}

// ---------------------------------------------------------------------------
// K0: build merged per-pair records {base pairs, w pairs} (48 B each).
// w reads are L2-resident (802 KB working set, read 64x).
// ---------------------------------------------------------------------------
__global__ void __launch_bounds__(256) k_base(
    const float* __restrict__ imgs, const float* __restrict__ noise,
    const float* __restrict__ w)
{
    int idx = blockIdx.x * 256 + threadIdx.x;        // 64*25088 = 1605632
    int b = idx / NPAIRS;
    int q = idx - b * NPAIRS;
    int p  = 2 * q;
    int j0 = b * IMG + p;
    const float2 i0 = *reinterpret_cast<const float2*>(imgs + j0);
    const float2 i1 = *reinterpret_cast<const float2*>(imgs + j0 + NPIX);
    const float2 i2 = *reinterpret_cast<const float2*>(imgs + j0 + 2*NPIX);
    const float2 n0 = *reinterpret_cast<const float2*>(noise + j0);
    const float2 n1 = *reinterpret_cast<const float2*>(noise + j0 + NPIX);
    const float2 n2 = *reinterpret_cast<const float2*>(noise + j0 + 2*NPIX);
    const float2 w0 = *reinterpret_cast<const float2*>(w + p);
    const float2 w1 = *reinterpret_cast<const float2*>(w + p + NPIX);
    const float2 w2 = *reinterpret_cast<const float2*>(w + p + 2*NPIX);
    float4 r0, r1, r2;
    r0.x = i0.x + n0.x;  r0.y = i0.y + n0.y;
    r0.z = i1.x + n1.x;  r0.w = i1.y + n1.y;
    r1.x = i2.x + n2.x;  r1.y = i2.y + n2.y;
    r1.z = w0.x;         r1.w = w0.y;
    r2.x = w1.x;  r2.y = w1.y;  r2.z = w2.x;  r2.w = w2.y;
    g_bw[(size_t)idx * 3]     = r0;
    g_bw[(size_t)idx * 3 + 1] = r1;
    g_bw[(size_t)idx * 3 + 2] = r2;
}

// ---------------------------------------------------------------------------
// K1: grid (NSEG, BATCH, NUM_IT+1). Each block: one 1/7 pixel segment of one
// (iter, image) tile: exactly 14 loop iters (3584 pairs = 14*256).
// Operand loads: 3x LDG.128 per pair (merged base+w records).
// ---------------------------------------------------------------------------
__global__ void __launch_bounds__(256, 8) k_logits(Keys keys, unsigned int one)
{
    const int seg = blockIdx.x;          // pixel segment: 0..6
    const int b   = blockIdx.y;
    const int it  = blockIdx.z;
    const int tid = threadIdx.x;
    const int base = b * IMG;
    const int qbeg = seg * SEG_PAIRS + tid;
    const int qend = (seg + 1) * SEG_PAIRS;
    const float4* __restrict__ bwp = g_bw + (size_t)b * NPAIRS * 3;

    float acc = 0.0f;
    if (it < NUM_IT) {
        const unsigned int k0 = keys.k[2 * it], k1 = keys.k[2 * it + 1];
        const unsigned int k2 = k0 ^ k1 ^ 0x1BD11BDAu;
        unsigned int* __restrict__ tdst = g_tn_h + ((size_t)it * BATCH + b) * NPIX;
        #pragma unroll 1
        for (int q = qbeg; q < qend; q += 256) {
            const int p  = 2 * q;
            const int j0 = base + p;
            // 6 hashes: 2 pixels x 3 channels
            u64 t0 = normal2(rbits_m(k0,k1,k2,(unsigned)j0,           one),
                             rbits_m(k0,k1,k2,(unsigned)(j0+1),       one));
            u64 t1 = normal2(rbits_m(k0,k1,k2,(unsigned)(j0+NPIX),    one),
                             rbits_m(k0,k1,k2,(unsigned)(j0+NPIX+1),  one));
            u64 t2 = normal2(rbits_m(k0,k1,k2,(unsigned)(j0+2*NPIX),  one),
                             rbits_m(k0,k1,k2,(unsigned)(j0+2*NPIX+1),one));
            // channel normalization, packed across the pixel pair
            u64 sum   = add2(add2(t0, t1), t2);
            u64 negmu = mul2(sum, sp2(-1.0f / 3.0f));
            u64 d0 = add2(t0, negmu), d1 = add2(t1, negmu), d2 = add2(t2, negmu);
            u64 var = mul2(d0, d0);
            var = fma2(d1, d1, var);
            var = fma2(d2, d2, var);                   // = 2 * var(ddof=1)
            // sc = sigma*sqrt(2)/sqrt(2var) = rsqrt(2var * 200)
            u64 varK = mul2(var, sp2(200.0f));
            float va_, vb_; upk2(varK, va_, vb_);
            u64 sc = pk2(rsqrtf(va_), rsqrtf(vb_));
            u64 tn0 = mul2(d0, sc), tn1 = mul2(d1, sc), tn2 = mul2(d2, sc);

            // store half2(ch0, ch1) per pixel as one STG.64 for the pair
            float x0a, x0b, x1a, x1b;
            upk2(tn0, x0a, x0b); upk2(tn1, x1a, x1b);
            __half2 hA = __floats2half2_rn(x0a, x1a);
            __half2 hB = __floats2half2_rn(x0b, x1b);
            uint2 st;
            st.x = *reinterpret_cast<unsigned int*>(&hA);
            st.y = *reinterpret_cast<unsigned int*>(&hB);
            *reinterpret_cast<uint2*>(tdst + p) = st;

            // dot: 3x LDG.128 merged operands, clip folded into FADD.SAT
            float x2a, x2b; upk2(tn2, x2a, x2b);
            const float4 r0 = bwp[(size_t)q * 3];
            const float4 r1 = bwp[(size_t)q * 3 + 1];
            const float4 r2 = bwp[(size_t)q * 3 + 2];
            acc = fmaf(addsat(r0.x, x0a), r1.z, acc);
            acc = fmaf(addsat(r0.y, x0b), r1.w, acc);
            acc = fmaf(addsat(r0.z, x1a), r2.x, acc);
            acc = fmaf(addsat(r0.w, x1b), r2.y, acc);
            acc = fmaf(addsat(r1.x, x2a), r2.z, acc);
            acc = fmaf(addsat(r1.y, x2b), r2.w, acc);
        }
    } else {
        #pragma unroll 1
        for (int q = qbeg; q < qend; q += 256) {
            const float4 r0 = bwp[(size_t)q * 3];
            const float4 r1 = bwp[(size_t)q * 3 + 1];
            const float4 r2 = bwp[(size_t)q * 3 + 2];
            acc = fmaf(sat(r0.x), r1.z, acc);
            acc = fmaf(sat(r0.y), r1.w, acc);
            acc = fmaf(sat(r0.z), r2.x, acc);
            acc = fmaf(sat(r0.w), r2.y, acc);
            acc = fmaf(sat(r1.x), r2.z, acc);
            acc = fmaf(sat(r1.y), r2.w, acc);
        }
    }

    __shared__ float red[256];
    red[tid] = acc;
    __syncthreads();
    #pragma unroll
    for (int s = 128; s > 32; s >>= 1) {
        if (tid < s) red[tid] += red[tid + s];
        __syncthreads();
    }
    if (tid < 32) {
        float v = red[tid] + red[tid + 32];
        #pragma unroll
        for (int o = 16; o > 0; o >>= 1)
            v += __shfl_down_sync(0xFFFFFFFFu, v, o);
        if (tid == 0) g_logits_part[seg][it * BATCH + b] = v;
    }
}

// ---------------------------------------------------------------------------
// K2: parallel — grid(BATCH) blocks x 64 threads (one per iteration).
// ---------------------------------------------------------------------------
__global__ void __launch_bounds__(64) k_dvals(const float* __restrict__ b_dnet)
{
    const int b = blockIdx.x;
    const int i = threadIdx.x;           // iteration 0..63
    float bb = b_dnet[0];

    float l2 = 0.0f;
    #pragma unroll
    for (int s = 0; s < NSEG; s++) l2 += g_logits_part[s][NUM_IT * BATCH + b];
    float p2 = 1.0f / (1.0f + expf(-(l2 + bb)));

    float li = 0.0f;
    #pragma unroll
    for (int s = 0; s < NSEG; s++) li += g_logits_part[s][i * BATCH + b];
    float pi = 1.0f / (1.0f + expf(-(li + bb)));
    float d = p2 - pi;
    g_d[i * BATCH + b] = d;

    float v = d * d;
    #pragma unroll
    for (int o = 16; o > 0; o >>= 1)
        v += __shfl_down_sync(0xFFFFFFFFu, v, o);
    __shared__ float part[2];
    if ((i & 31) == 0) part[i >> 5] = v;
    __syncthreads();
    if (i == 0) {
        float nc = part[0] + part[1];
        g_coef[b] = 1.0f / ((float)NUM_IT * (sqrtf(nc) + 1e-10f) * SIGMA_F);
    }
}

// ---------------------------------------------------------------------------
// K3: per-pixel output; stream precomputed half2 tn (822 MB read, DRAM-bound)
// ---------------------------------------------------------------------------
__global__ void __launch_bounds__(256) k_output(float* __restrict__ out)
{
    __shared__ float dsh[NUM_IT];
    const int b = blockIdx.y;
    if (threadIdx.x < NUM_IT) dsh[threadIdx.x] = g_d[threadIdx.x * BATCH + b];
    __syncthreads();

    const int p = blockIdx.x * 256 + threadIdx.x;
    const size_t stride = (size_t)BATCH * NPIX;
    const unsigned int* __restrict__ tp = g_tn_h + (size_t)b * NPIX + p;

    float a0 = 0.0f, a1 = 0.0f, a2 = 0.0f;
    #pragma unroll 8
    for (int i = 0; i < NUM_IT; i++) {
        unsigned int hb = tp[i * stride];
        __half2 h = *reinterpret_cast<__half2*>(&hb);
        float2 tn = __half22float2(h);
        float di = dsh[i];
        a0 = fmaf(tn.x, di, a0);
        a1 = fmaf(tn.y, di, a1);
        a2 = fmaf(-(tn.x + tn.y), di, a2);
    }
    float c = g_coef[b];
    const int j0 = b * IMG + p;
    out[j0]            = a0 * c;
    out[j0 + NPIX]     = a1 * c;
    out[j0 + 2 * NPIX] = a2 * c;
}

// ---------------------------------------------------------------------------
extern "C" void kernel_launch(void* const* d_in, const int* in_sizes, int n_in,
                              void* d_out, int out_size)
{
    const float* imgs  = (const float*)d_in[0];
    const float* noise = (const float*)d_in[1];
    const float* w     = (const float*)d_in[2];
    const float* bb    = (const float*)d_in[3];
    float* out = (float*)d_out;

    // keys = jax.random.split(jax.random.key(42), 64); base key data (0, 42)
    Keys keys;
    for (int i = 0; i < NUM_IT; i++) {
        unsigned int o0, o1;
        tf2x32_host(0u, 42u, 0u, (unsigned)i, o0, o1);
        keys.k[2 * i] = o0; keys.k[2 * i + 1] = o1;
    }

    k_base<<<(BATCH * NPAIRS) / 256, 256>>>(imgs, noise, w);  // 6272 blocks

    dim3 g1(NSEG, BATCH, NUM_IT + 1);   // 7 x 64 x 65 = 29120 blocks
    k_logits<<<g1, 256>>>(keys, 1u);

    k_dvals<<<BATCH, 64>>>(bb);

    dim3 g3(NPIX / 256, BATCH);   // 50176 = 196 * 256 exactly
    k_output<<<g3, 256>>>(out);
}